// round 2
// baseline (speedup 1.0000x reference)
#include <cuda_runtime.h>
#include <math.h>

// ---------------------------------------------------------------------------
// TransformerEncoderLayer: B=2, S=2048, D=1024, H=16, dh=64, F=2048, fp32.
// Only batch 0 of attention output is used (reference: src2 = attn_out[0]),
// so the attention path runs with M=2048.
// ---------------------------------------------------------------------------

#define SEQ   2048
#define DMOD  1024
#define DFF   2048
#define NHEAD 16
#define DH    64
#define M_ATT 2048   /* batch 0 only */
#define M_ALL 4096   /* both batches */

// Scratch (device globals; allocation-free per harness rules)
__device__ float g_qkv[3 * M_ATT * DMOD];   // q | k | v contiguous
__device__ float g_ctx[M_ATT * DMOD];
__device__ float g_att[M_ATT * DMOD];
__device__ float g_x  [M_ALL * DMOD];
__device__ float g_h1 [M_ALL * DFF ];
__device__ float g_f2 [M_ALL * DMOD];

__device__ __forceinline__ float gelu_exact(float x) {
    return 0.5f * x * (1.0f + erff(x * 0.70710678118654752f));
}

// ---------------------------------------------------------------------------
// SGEMM: C[M,N] = act(A[M,K] @ B[K,N] + bias[N])
// 128x128 block tile, BK=8, 256 threads, 8x8 per thread.
// Double-buffered smem: one __syncthreads per K-slab.
// M,N % 128 == 0, K % 8 == 0. act: 0 = none, 1 = exact GELU.
// ---------------------------------------------------------------------------
__global__ __launch_bounds__(256, 2)
void sgemm_bias(const float* __restrict__ A, const float* __restrict__ B,
                const float* __restrict__ bias, float* __restrict__ C,
                int M, int N, int K, int act)
{
    __shared__ float As[2][8][128];
    __shared__ float Bs[2][8][128];

    const int tid = threadIdx.x;
    const int bx = blockIdx.x, by = blockIdx.y;

    const float* Ab = A + by * 128 * K;
    const float* Bb = B + bx * 128;

    const int arow = tid >> 1;          // 0..127
    const int acol = (tid & 1) << 2;    // 0 or 4
    const int brow = tid >> 5;          // 0..7
    const int bcol = (tid & 31) << 2;   // 0..124

    const int tx = (tid & 15) << 3;     // output col offset 0..120
    const int ty = (tid >> 4) << 3;     // output row offset 0..120

    float acc[8][8];
    #pragma unroll
    for (int i = 0; i < 8; ++i)
        #pragma unroll
        for (int j = 0; j < 8; ++j) acc[i][j] = 0.0f;

    // Preload slab 0 into buffer 0
    {
        float4 a4 = *(const float4*)(Ab + arow * K + acol);
        float4 b4 = *(const float4*)(Bb + brow * N + bcol);
        As[0][acol + 0][arow] = a4.x;
        As[0][acol + 1][arow] = a4.y;
        As[0][acol + 2][arow] = a4.z;
        As[0][acol + 3][arow] = a4.w;
        *(float4*)&Bs[0][brow][bcol] = b4;
    }
    __syncthreads();

    int buf = 0;
    for (int k0 = 0; k0 < K; k0 += 8) {
        const int knx = k0 + 8;
        float4 a4, b4;
        const bool more = (knx < K);
        if (more) {
            a4 = *(const float4*)(Ab + arow * K + knx + acol);
            b4 = *(const float4*)(Bb + (knx + brow) * N + bcol);
        }

        #pragma unroll
        for (int kk = 0; kk < 8; ++kk) {
            float af[8], bf[8];
            *(float4*)(af)     = *(const float4*)&As[buf][kk][ty];
            *(float4*)(af + 4) = *(const float4*)&As[buf][kk][ty + 4];
            *(float4*)(bf)     = *(const float4*)&Bs[buf][kk][tx];
            *(float4*)(bf + 4) = *(const float4*)&Bs[buf][kk][tx + 4];
            #pragma unroll
            for (int i = 0; i < 8; ++i)
                #pragma unroll
                for (int j = 0; j < 8; ++j)
                    acc[i][j] = fmaf(af[i], bf[j], acc[i][j]);
        }

        if (more) {
            const int nb = buf ^ 1;
            As[nb][acol + 0][arow] = a4.x;
            As[nb][acol + 1][arow] = a4.y;
            As[nb][acol + 2][arow] = a4.z;
            As[nb][acol + 3][arow] = a4.w;
            *(float4*)&Bs[nb][brow][bcol] = b4;
            __syncthreads();
            buf = nb;
        }
    }

    #pragma unroll
    for (int i = 0; i < 8; ++i) {
        const int row = by * 128 + ty + i;
        #pragma unroll
        for (int j = 0; j < 8; j += 4) {
            const int col = bx * 128 + tx + j;
            float4 o;
            o.x = acc[i][j + 0] + bias[col + 0];
            o.y = acc[i][j + 1] + bias[col + 1];
            o.z = acc[i][j + 2] + bias[col + 2];
            o.w = acc[i][j + 3] + bias[col + 3];
            if (act) {
                o.x = gelu_exact(o.x); o.y = gelu_exact(o.y);
                o.z = gelu_exact(o.z); o.w = gelu_exact(o.w);
            }
            *(float4*)(C + row * N + col) = o;
        }
    }
}

// ---------------------------------------------------------------------------
// Fused QKV projection: one launch computes q|k|v into g_qkv.
// grid.x in [0, 3*DMOD/128): selects which weight/bias/output via bx/8.
// Shares the A (src) tiles in L2 across all three projections.
// ---------------------------------------------------------------------------
__global__ __launch_bounds__(256, 2)
void sgemm_qkv(const float* __restrict__ A,
               const float* __restrict__ Wq, const float* __restrict__ bq,
               const float* __restrict__ Wk, const float* __restrict__ bk,
               const float* __restrict__ Wv, const float* __restrict__ bv,
               float* __restrict__ Out)
{
    __shared__ float As[2][8][128];
    __shared__ float Bs[2][8][128];

    const int tid = threadIdx.x;
    const int bxg = blockIdx.x;          // 0..23
    const int which = bxg >> 3;          // 0=q, 1=k, 2=v
    const int bx = bxg & 7;              // column tile within D
    const int by = blockIdx.y;

    const float* B    = (which == 0) ? Wq : (which == 1) ? Wk : Wv;
    const float* bias = (which == 0) ? bq : (which == 1) ? bk : bv;
    float* C = Out + which * (M_ATT * DMOD);

    const int K = DMOD, N = DMOD;
    const float* Ab = A + by * 128 * K;
    const float* Bb = B + bx * 128;

    const int arow = tid >> 1;
    const int acol = (tid & 1) << 2;
    const int brow = tid >> 5;
    const int bcol = (tid & 31) << 2;
    const int tx = (tid & 15) << 3;
    const int ty = (tid >> 4) << 3;

    float acc[8][8];
    #pragma unroll
    for (int i = 0; i < 8; ++i)
        #pragma unroll
        for (int j = 0; j < 8; ++j) acc[i][j] = 0.0f;

    {
        float4 a4 = *(const float4*)(Ab + arow * K + acol);
        float4 b4 = *(const float4*)(Bb + brow * N + bcol);
        As[0][acol + 0][arow] = a4.x;
        As[0][acol + 1][arow] = a4.y;
        As[0][acol + 2][arow] = a4.z;
        As[0][acol + 3][arow] = a4.w;
        *(float4*)&Bs[0][brow][bcol] = b4;
    }
    __syncthreads();

    int buf = 0;
    for (int k0 = 0; k0 < K; k0 += 8) {
        const int knx = k0 + 8;
        float4 a4, b4;
        const bool more = (knx < K);
        if (more) {
            a4 = *(const float4*)(Ab + arow * K + knx + acol);
            b4 = *(const float4*)(Bb + (knx + brow) * N + bcol);
        }

        #pragma unroll
        for (int kk = 0; kk < 8; ++kk) {
            float af[8], bf[8];
            *(float4*)(af)     = *(const float4*)&As[buf][kk][ty];
            *(float4*)(af + 4) = *(const float4*)&As[buf][kk][ty + 4];
            *(float4*)(bf)     = *(const float4*)&Bs[buf][kk][tx];
            *(float4*)(bf + 4) = *(const float4*)&Bs[buf][kk][tx + 4];
            #pragma unroll
            for (int i = 0; i < 8; ++i)
                #pragma unroll
                for (int j = 0; j < 8; ++j)
                    acc[i][j] = fmaf(af[i], bf[j], acc[i][j]);
        }

        if (more) {
            const int nb = buf ^ 1;
            As[nb][acol + 0][arow] = a4.x;
            As[nb][acol + 1][arow] = a4.y;
            As[nb][acol + 2][arow] = a4.z;
            As[nb][acol + 3][arow] = a4.w;
            *(float4*)&Bs[nb][brow][bcol] = b4;
            __syncthreads();
            buf = nb;
        }
    }

    #pragma unroll
    for (int i = 0; i < 8; ++i) {
        const int row = by * 128 + ty + i;
        #pragma unroll
        for (int j = 0; j < 8; j += 4) {
            const int col = bx * 128 + tx + j;
            float4 o;
            o.x = acc[i][j + 0] + bias[col + 0];
            o.y = acc[i][j + 1] + bias[col + 1];
            o.z = acc[i][j + 2] + bias[col + 2];
            o.w = acc[i][j + 3] + bias[col + 3];
            *(float4*)(C + row * N + col) = o;
        }
    }
}

// ---------------------------------------------------------------------------
// Flash attention, b=0 only. Grid (S/64, H), 256 threads.
// Q/K/V layout: [S, DMOD], head h occupies columns h*64 .. h*64+63.
// Tiles 64x64, online softmax, output ctx[S, DMOD] same layout.
// K stored XOR-swizzled (per 8-row group); its buffer is reused for P.
// ---------------------------------------------------------------------------
__global__ __launch_bounds__(256, 2)
void flash_attn(const float* __restrict__ Q, const float* __restrict__ K,
                const float* __restrict__ V, float* __restrict__ O)
{
    __shared__ float Qs[64 * 64];
    __shared__ float Ks[64 * 64];   // swizzled K; reused (natural layout) for P
    __shared__ float Vs[64 * 64];

    const int tid = threadIdx.x;
    const int tx  = tid & 15;
    const int ty  = tid >> 4;
    const int h   = blockIdx.y;
    const int q0  = blockIdx.x * 64;

    const int lr = tid >> 4;          // load row base 0..15
    const int lc = (tid & 15) << 2;   // load col 0..60 (float4)

    // Load Q tile (natural layout)
    #pragma unroll
    for (int rr = 0; rr < 4; ++rr) {
        const int r = lr + rr * 16;
        float4 v4 = *(const float4*)(Q + (q0 + r) * DMOD + h * DH + lc);
        *(float4*)&Qs[r * 64 + lc] = v4;
    }

    const int qr0 = ty * 4;   // this thread's 4 query rows
    const int kc0 = tx * 4;   // this thread's 4 key cols / output cols

    float m[4], l[4], o[4][4];
    #pragma unroll
    for (int i = 0; i < 4; ++i) {
        m[i] = -1e30f; l[i] = 0.0f;
        #pragma unroll
        for (int j = 0; j < 4; ++j) o[i][j] = 0.0f;
    }

    for (int kt = 0; kt < SEQ; kt += 64) {
        // Load K (swizzled) and V (natural)
        #pragma unroll
        for (int rr = 0; rr < 4; ++rr) {
            const int r  = lr + rr * 16;
            const int sw = (r >> 3) << 2;   // 0,4,...,28 per 8-row group
            float4 kv = *(const float4*)(K + (kt + r) * DMOD + h * DH + lc);
            *(float4*)&Ks[r * 64 + (lc ^ sw)] = kv;
            float4 vv = *(const float4*)(V + (kt + r) * DMOD + h * DH + lc);
            *(float4*)&Vs[r * 64 + lc] = vv;
        }
        __syncthreads();

        // Scores s[i][j] = sum_d Q[qr0+i][d] * K[kc0+j][d]
        float s[4][4];
        #pragma unroll
        for (int i = 0; i < 4; ++i)
            #pragma unroll
            for (int j = 0; j < 4; ++j) s[i][j] = 0.0f;

        #pragma unroll 4
        for (int d = 0; d < 64; d += 4) {
            float a[4][4], b[4][4];
            #pragma unroll
            for (int i = 0; i < 4; ++i) {
                float4 t = *(const float4*)&Qs[(qr0 + i) * 64 + d];
                a[i][0] = t.x; a[i][1] = t.y; a[i][2] = t.z; a[i][3] = t.w;
            }
            #pragma unroll
            for (int j = 0; j < 4; ++j) {
                const int kr = kc0 + j;
                const int sw = (kr >> 3) << 2;
                float4 t = *(const float4*)&Ks[kr * 64 + (d ^ sw)];
                b[j][0] = t.x; b[j][1] = t.y; b[j][2] = t.z; b[j][3] = t.w;
            }
            #pragma unroll
            for (int i = 0; i < 4; ++i)
                #pragma unroll
                for (int j = 0; j < 4; ++j)
                    s[i][j] += a[i][0]*b[j][0] + a[i][1]*b[j][1]
                             + a[i][2]*b[j][2] + a[i][3]*b[j][3];
        }
        __syncthreads();   // done reading Ks; it becomes the P buffer

        // Online softmax update (scale 1/sqrt(64) = 0.125)
        #pragma unroll
        for (int i = 0; i < 4; ++i) {
            #pragma unroll
            for (int j = 0; j < 4; ++j) s[i][j] *= 0.125f;

            float rm = fmaxf(fmaxf(s[i][0], s[i][1]), fmaxf(s[i][2], s[i][3]));
            #pragma unroll
            for (int w = 8; w; w >>= 1)
                rm = fmaxf(rm, __shfl_xor_sync(0xffffffffu, rm, w));

            const float nm   = fmaxf(m[i], rm);
            const float corr = __expf(m[i] - nm);
            m[i] = nm;

            float rs = 0.0f;
            #pragma unroll
            for (int j = 0; j < 4; ++j) {
                s[i][j] = __expf(s[i][j] - nm);
                rs += s[i][j];
            }
            #pragma unroll
            for (int w = 8; w; w >>= 1)
                rs += __shfl_xor_sync(0xffffffffu, rs, w);

            l[i] = l[i] * corr + rs;
            #pragma unroll
            for (int j = 0; j < 4; ++j) o[i][j] *= corr;

            *(float4*)&Ks[(qr0 + i) * 64 + kc0] =
                make_float4(s[i][0], s[i][1], s[i][2], s[i][3]);
        }
        __syncthreads();

        // o += P @ V
        #pragma unroll 4
        for (int kk = 0; kk < 64; kk += 4) {
            float p[4][4], vr[4][4];
            #pragma unroll
            for (int i = 0; i < 4; ++i) {
                float4 t = *(const float4*)&Ks[(qr0 + i) * 64 + kk];
                p[i][0] = t.x; p[i][1] = t.y; p[i][2] = t.z; p[i][3] = t.w;
            }
            #pragma unroll
            for (int c = 0; c < 4; ++c) {
                float4 t = *(const float4*)&Vs[(kk + c) * 64 + kc0];
                vr[c][0] = t.x; vr[c][1] = t.y; vr[c][2] = t.z; vr[c][3] = t.w;
            }
            #pragma unroll
            for (int i = 0; i < 4; ++i)
                #pragma unroll
                for (int j = 0; j < 4; ++j)
                    o[i][j] += p[i][0]*vr[0][j] + p[i][1]*vr[1][j]
                             + p[i][2]*vr[2][j] + p[i][3]*vr[3][j];
        }
        __syncthreads();   // protect Ks/Vs for next tile load
    }

    #pragma unroll
    for (int i = 0; i < 4; ++i) {
        const float inv = 1.0f / l[i];
        float4 ov = make_float4(o[i][0]*inv, o[i][1]*inv, o[i][2]*inv, o[i][3]*inv);
        *(float4*)(O + (q0 + qr0 + i) * DMOD + h * DH + kc0) = ov;
    }
}

// ---------------------------------------------------------------------------
// out[row] = LayerNorm(a[row] + b[row % bwrap]) * g + beta
// Grid = rows, 256 threads, D=1024 (4 floats/thread).
// ---------------------------------------------------------------------------
__global__ __launch_bounds__(256)
void ln_add(const float* __restrict__ a, const float* __restrict__ b, int bwrap,
            const float* __restrict__ g, const float* __restrict__ be,
            float* __restrict__ out)
{
    const int row  = blockIdx.x;
    const int brow = row % bwrap;
    const int t    = threadIdx.x;

    float4 av = ((const float4*)(a + row  * DMOD))[t];
    float4 bv = ((const float4*)(b + brow * DMOD))[t];
    const float x0 = av.x + bv.x, x1 = av.y + bv.y;
    const float x2 = av.z + bv.z, x3 = av.w + bv.w;

    float s  = x0 + x1 + x2 + x3;
    float ss = x0*x0 + x1*x1 + x2*x2 + x3*x3;

    #pragma unroll
    for (int w = 16; w; w >>= 1) {
        s  += __shfl_xor_sync(0xffffffffu, s,  w);
        ss += __shfl_xor_sync(0xffffffffu, ss, w);
    }

    __shared__ float rs[8], rss[8];
    if ((t & 31) == 0) { rs[t >> 5] = s; rss[t >> 5] = ss; }
    __syncthreads();

    float tot = 0.0f, tot2 = 0.0f;
    #pragma unroll
    for (int i = 0; i < 8; ++i) { tot += rs[i]; tot2 += rss[i]; }

    const float mu  = tot  * (1.0f / DMOD);
    const float var = tot2 * (1.0f / DMOD) - mu * mu;
    const float inv = rsqrtf(var + 1e-5f);

    float4 gv = ((const float4*)g )[t];
    float4 ev = ((const float4*)be)[t];
    float4 ov;
    ov.x = (x0 - mu) * inv * gv.x + ev.x;
    ov.y = (x1 - mu) * inv * gv.y + ev.y;
    ov.z = (x2 - mu) * inv * gv.z + ev.z;
    ov.w = (x3 - mu) * inv * gv.w + ev.w;
    ((float4*)(out + row * DMOD))[t] = ov;
}

// ---------------------------------------------------------------------------
extern "C" void kernel_launch(void* const* d_in, const int* in_sizes, int n_in,
                              void* d_out, int out_size)
{
    (void)in_sizes; (void)n_in; (void)out_size;

    const float* src  = (const float*)d_in[0];
    const float* w_q  = (const float*)d_in[1];
    const float* b_q  = (const float*)d_in[2];
    const float* w_k  = (const float*)d_in[3];
    const float* b_k  = (const float*)d_in[4];
    const float* w_v  = (const float*)d_in[5];
    const float* b_v  = (const float*)d_in[6];
    const float* w_o  = (const float*)d_in[7];
    const float* b_o  = (const float*)d_in[8];
    const float* ln1g = (const float*)d_in[9];
    const float* ln1b = (const float*)d_in[10];
    const float* ln2g = (const float*)d_in[11];
    const float* ln2b = (const float*)d_in[12];
    const float* w1   = (const float*)d_in[13];
    const float* bb1  = (const float*)d_in[14];
    const float* w2   = (const float*)d_in[15];
    const float* bb2  = (const float*)d_in[16];
    float* out = (float*)d_out;

    float *qkv, *ctx, *att, *x, *h1, *f2;
    cudaGetSymbolAddress((void**)&qkv, g_qkv);
    cudaGetSymbolAddress((void**)&ctx, g_ctx);
    cudaGetSymbolAddress((void**)&att, g_att);
    cudaGetSymbolAddress((void**)&x,   g_x);
    cudaGetSymbolAddress((void**)&h1,  g_h1);
    cudaGetSymbolAddress((void**)&f2,  g_f2);

    float* q = qkv;
    float* k = qkv + M_ATT * DMOD;
    float* v = qkv + 2 * M_ATT * DMOD;

    const dim3 blk(256);

    // Fused QKV projections (batch 0 only — src rows 0..2047)
    sgemm_qkv<<<dim3(3 * DMOD / 128, M_ATT / 128), blk>>>(
        src, w_q, b_q, w_k, b_k, w_v, b_v, qkv);

    // Attention (batch 0)
    flash_attn<<<dim3(SEQ / 64, NHEAD), blk>>>(q, k, v, ctx);

    // Output projection (batch 0)
    sgemm_bias<<<dim3(DMOD / 128, M_ATT / 128), blk>>>(ctx, w_o, b_o, att,
                                                       M_ATT, DMOD, DMOD, 0);

    // x = LN1(src + attn_out[0] broadcast)
    ln_add<<<M_ALL, 256>>>(src, att, SEQ, ln1g, ln1b, x);

    // FFN
    sgemm_bias<<<dim3(DFF / 128,  M_ALL / 128), blk>>>(x,  w1, bb1, h1,
                                                       M_ALL, DFF,  DMOD, 1);
    sgemm_bias<<<dim3(DMOD / 128, M_ALL / 128), blk>>>(h1, w2, bb2, f2,
                                                       M_ALL, DMOD, DFF,  0);

    // out = LN2(x + ffn)
    ln_add<<<M_ALL, 256>>>(x, f2, M_ALL, ln2g, ln2b, out);
}

// round 4
// speedup vs baseline: 1.7204x; 1.7204x over previous
#include <cuda_runtime.h>
#include <cuda_bf16.h>
#include <math.h>
#include <stdint.h>

// ---------------------------------------------------------------------------
// TransformerEncoderLayer: B=2, S=2048, D=1024, H=16, dh=64, F=2048, fp32.
// Only batch 0 of attention output is used (src2 = attn_out[0]).
// GEMMs: warp-level HMMA (mma.sync m16n8k16 bf16) with 2-term bf16 split
// (hi+lo -> hi*hi + lo*hi + hi*lo) for ~1e-5 accuracy.
// Attention + LayerNorm remain fp32 SIMT.
// NOTE: tcgen05 is rejected by this harness's ptxas target (sm_103, no 'a'),
// so baseline-ISA mma.sync is the fastest available tensor path.
// ---------------------------------------------------------------------------

#define SEQ   2048
#define DMOD  1024
#define DFF   2048
#define NHEAD 16
#define DH    64
#define M_ATT 2048
#define M_ALL 4096

typedef __nv_bfloat16 bf16;

// ------------------------- scratch (device globals) ------------------------
__device__ bf16  g_src_h[M_ATT * DMOD],  g_src_l[M_ATT * DMOD];
__device__ bf16  g_wqkv_h[3 * DMOD * DMOD], g_wqkv_l[3 * DMOD * DMOD]; // [3072,1024] K-major
__device__ float g_bqkv[3 * DMOD];
__device__ bf16  g_wo_h[DMOD * DMOD],   g_wo_l[DMOD * DMOD];
__device__ bf16  g_w1_h[DFF * DMOD],    g_w1_l[DFF * DMOD];
__device__ bf16  g_w2_h[DMOD * DFF],    g_w2_l[DMOD * DFF];
__device__ float g_qkv[M_ATT * 3 * DMOD];
__device__ float g_ctx[M_ATT * DMOD];
__device__ bf16  g_ctx_h[M_ATT * DMOD], g_ctx_l[M_ATT * DMOD];
__device__ float g_att[M_ATT * DMOD];
__device__ float g_x  [M_ALL * DMOD];
__device__ bf16  g_x_h [M_ALL * DMOD],  g_x_l [M_ALL * DMOD];
__device__ float g_h1 [M_ALL * DFF];
__device__ bf16  g_h1_h[M_ALL * DFF],   g_h1_l[M_ALL * DFF];
__device__ float g_f2 [M_ALL * DMOD];

// ------------------------------ helpers ------------------------------------
__device__ __forceinline__ uint32_t smem_to_u32(const void* p) {
    uint32_t a;
    asm("{ .reg .u64 t; cvta.to.shared.u64 t, %1; cvt.u32.u64 %0, t; }"
        : "=r"(a) : "l"(p));
    return a;
}
__device__ __forceinline__ void cp16(uint32_t d, const void* s) {
    asm volatile("cp.async.cg.shared.global [%0], [%1], 16;" :: "r"(d), "l"(s));
}
__device__ __forceinline__ void ldsm4(uint32_t r[4], uint32_t addr) {
    asm volatile("ldmatrix.sync.aligned.m8n8.x4.shared.b16 {%0,%1,%2,%3}, [%4];"
                 : "=r"(r[0]), "=r"(r[1]), "=r"(r[2]), "=r"(r[3]) : "r"(addr));
}
#define MMA16816(d, a, b) \
    asm volatile("mma.sync.aligned.m16n8k16.row.col.f32.bf16.bf16.f32 " \
        "{%0,%1,%2,%3}, {%4,%5,%6,%7}, {%8,%9}, {%0,%1,%2,%3};" \
        : "+f"((d)[0]), "+f"((d)[1]), "+f"((d)[2]), "+f"((d)[3]) \
        : "r"((a)[0]), "r"((a)[1]), "r"((a)[2]), "r"((a)[3]), \
          "r"((b)[0]), "r"((b)[1]))

// 128x32-bf16 tile in smem: row = 64B; 16B segment swizzled so any ldmatrix
// (8 rows x 16B) hits 8 distinct 16B groups mod 128B.
#define SWZ(row, seg) (((row) << 6) + (((seg) ^ (((row) >> 1) & 3)) << 4))

__device__ __forceinline__ float gelu_exact(float x) {
    return 0.5f * x * (1.0f + erff(x * 0.70710678118654752f));
}

// ---------------------------------------------------------------------------
// HMMA GEMM: C[M,N] = act(Asplit @ Bsplit^T + bias)
//   A* : [M,K] bf16 K-major (hi, lo); B* : [N,K] bf16 K-major (hi, lo).
// CTA tile 128x128, 8 warps (2m x 4n), warp tile 64x32, K-chunk 32,
// cp.async double-buffered smem (2 x 32KB). K % 32 == 0.
// ---------------------------------------------------------------------------
#define GM_SMEM 65536

__global__ __launch_bounds__(256, 1)
void gemm_mma(const bf16* __restrict__ Ahi, const bf16* __restrict__ Alo,
              const bf16* __restrict__ Bhi, const bf16* __restrict__ Blo,
              const float* __restrict__ bias, float* __restrict__ C,
              int M, int N, int K, int act)
{
    extern __shared__ char sm[];
    const uint32_t smb = smem_to_u32(sm);
    const int tid  = threadIdx.x;
    const int lane = tid & 31;
    const int wid  = tid >> 5;
    const int wm   = wid >> 2;          // 0..1
    const int wn   = wid & 3;           // 0..3
    const int m0 = blockIdx.y * 128;
    const int n0 = blockIdx.x * 128;

    const char* gAh = (const char*)(Ahi + (size_t)m0 * K);
    const char* gAl = (const char*)(Alo + (size_t)m0 * K);
    const char* gBh = (const char*)(Bhi + (size_t)n0 * K);
    const char* gBl = (const char*)(Blo + (size_t)n0 * K);

    const int lrow = tid >> 2;          // 0..63  (with i: +64)
    const int lseg = tid & 3;

    float acc[4][4][4];
    #pragma unroll
    for (int i = 0; i < 4; ++i)
        #pragma unroll
        for (int j = 0; j < 4; ++j)
            #pragma unroll
            for (int q = 0; q < 4; ++q) acc[i][j][q] = 0.0f;

    const int nch = K >> 5;

    // --- issue chunk loads (8 cp.async of 16B per thread) ---
    auto issue = [&](int ch, int buf) {
        const int k0 = ch << 5;
        #pragma unroll
        for (int i = 0; i < 2; ++i) {
            const int row = lrow + (i << 6);
            const uint32_t so = SWZ(row, lseg) + (uint32_t)buf * 32768 + smb;
            const size_t go = (size_t)row * K * 2 + (size_t)(k0 + lseg * 8) * 2;
            cp16(so +     0, gAh + go);
            cp16(so +  8192, gAl + go);
            cp16(so + 16384, gBh + go);
            cp16(so + 24576, gBl + go);
        }
        asm volatile("cp.async.commit_group;" ::: "memory");
    };

    issue(0, 0);

    const int arow = wm * 64 + (lane & 15);
    const int aseg0 = (lane >> 4);                       // 0/1
    const int brow = wn * 32 + (lane & 7) + ((lane >> 4) & 1) * 8;
    const int bseg0 = ((lane >> 3) & 1);                 // 0/1

    for (int ch = 0; ch < nch; ++ch) {
        const int buf = ch & 1;
        if (ch + 1 < nch) {
            issue(ch + 1, buf ^ 1);
            asm volatile("cp.async.wait_group 1;" ::: "memory");
        } else {
            asm volatile("cp.async.wait_group 0;" ::: "memory");
        }
        __syncthreads();

        const uint32_t Ah = smb + (uint32_t)buf * 32768;
        const uint32_t Al = Ah + 8192;
        const uint32_t Bh = Ah + 16384;
        const uint32_t Bl = Ah + 24576;

        #pragma unroll
        for (int ks = 0; ks < 2; ++ks) {
            const int asg = ks * 2 + aseg0;
            const int bsg = ks * 2 + bseg0;
            uint32_t af[4][4], al[4][4], bfr[4][2];

            #pragma unroll
            for (int ti = 0; ti < 4; ++ti)
                ldsm4(af[ti], Ah + SWZ(arow + ti * 16, asg));
            #pragma unroll
            for (int p = 0; p < 2; ++p) {
                uint32_t r[4];
                ldsm4(r, Bh + SWZ(brow + p * 16, bsg));
                bfr[2*p][0] = r[0]; bfr[2*p][1] = r[1];
                bfr[2*p+1][0] = r[2]; bfr[2*p+1][1] = r[3];
            }
            #pragma unroll
            for (int ti = 0; ti < 4; ++ti)
                #pragma unroll
                for (int tj = 0; tj < 4; ++tj)
                    MMA16816(acc[ti][tj], af[ti], bfr[tj]);     // hi*hi

            #pragma unroll
            for (int ti = 0; ti < 4; ++ti)
                ldsm4(al[ti], Al + SWZ(arow + ti * 16, asg));
            #pragma unroll
            for (int ti = 0; ti < 4; ++ti)
                #pragma unroll
                for (int tj = 0; tj < 4; ++tj)
                    MMA16816(acc[ti][tj], al[ti], bfr[tj]);     // lo*hi

            #pragma unroll
            for (int p = 0; p < 2; ++p) {
                uint32_t r[4];
                ldsm4(r, Bl + SWZ(brow + p * 16, bsg));
                bfr[2*p][0] = r[0]; bfr[2*p][1] = r[1];
                bfr[2*p+1][0] = r[2]; bfr[2*p+1][1] = r[3];
            }
            #pragma unroll
            for (int ti = 0; ti < 4; ++ti)
                #pragma unroll
                for (int tj = 0; tj < 4; ++tj)
                    MMA16816(acc[ti][tj], af[ti], bfr[tj]);     // hi*lo
        }
        __syncthreads();
    }

    // --- epilogue: bias (+gelu), direct stores ---
    const int g = lane >> 2, t = lane & 3;
    #pragma unroll
    for (int tj = 0; tj < 4; ++tj) {
        const int c = n0 + wn * 32 + tj * 8 + 2 * t;
        const float2 b2 = *(const float2*)&bias[c];
        #pragma unroll
        for (int ti = 0; ti < 4; ++ti) {
            const int r0 = m0 + wm * 64 + ti * 16 + g;
            float2 v0 = make_float2(acc[ti][tj][0] + b2.x, acc[ti][tj][1] + b2.y);
            float2 v1 = make_float2(acc[ti][tj][2] + b2.x, acc[ti][tj][3] + b2.y);
            if (act) {
                v0.x = gelu_exact(v0.x); v0.y = gelu_exact(v0.y);
                v1.x = gelu_exact(v1.x); v1.y = gelu_exact(v1.y);
            }
            *(float2*)(C + (size_t)r0 * N + c) = v0;
            *(float2*)(C + (size_t)(r0 + 8) * N + c) = v1;
        }
    }
}

// ---------------------------------------------------------------------------
// fp32 -> (hi, lo) bf16 split, elementwise, vectorized x4.
// ---------------------------------------------------------------------------
__global__ __launch_bounds__(256)
void split_f32(const float4* __restrict__ in, bf16* __restrict__ hi,
               bf16* __restrict__ lo, int n4)
{
    const int i = blockIdx.x * 256 + threadIdx.x;
    if (i >= n4) return;
    const float4 x = in[i];
    __nv_bfloat162 h01 = __floats2bfloat162_rn(x.x, x.y);
    __nv_bfloat162 h23 = __floats2bfloat162_rn(x.z, x.w);
    float2 f01 = __bfloat1622float2(h01);
    float2 f23 = __bfloat1622float2(h23);
    __nv_bfloat162 l01 = __floats2bfloat162_rn(x.x - f01.x, x.y - f01.y);
    __nv_bfloat162 l23 = __floats2bfloat162_rn(x.z - f23.x, x.w - f23.y);
    ((__nv_bfloat162*)hi)[2 * i]     = h01;
    ((__nv_bfloat162*)hi)[2 * i + 1] = h23;
    ((__nv_bfloat162*)lo)[2 * i]     = l01;
    ((__nv_bfloat162*)lo)[2 * i + 1] = l23;
}

// ---------------------------------------------------------------------------
// W[K,N] fp32 -> Wt hi/lo [rowOff + N rows, outLd] bf16 (transposed, split).
// Block (32, 8), grid (N/32, K/32).
// ---------------------------------------------------------------------------
__global__ __launch_bounds__(256)
void trans_split(const float* __restrict__ W, bf16* __restrict__ hi,
                 bf16* __restrict__ lo, int K, int N, int rowOff, int outLd)
{
    __shared__ float t[32][33];
    const int k0 = blockIdx.y * 32, n0 = blockIdx.x * 32;
    const int tx = threadIdx.x, ty = threadIdx.y;
    #pragma unroll
    for (int i = 0; i < 32; i += 8)
        t[ty + i][tx] = W[(size_t)(k0 + ty + i) * N + n0 + tx];
    __syncthreads();
    #pragma unroll
    for (int i = 0; i < 32; i += 8) {
        const float x = t[tx][ty + i];
        const bf16 h = __float2bfloat16(x);
        const bf16 l = __float2bfloat16(x - __bfloat162float(h));
        const size_t o = (size_t)(rowOff + n0 + ty + i) * outLd + k0 + tx;
        hi[o] = h;
        lo[o] = l;
    }
}

__global__ void pack_bias3(const float* __restrict__ a, const float* __restrict__ b,
                           const float* __restrict__ c, float* __restrict__ out)
{
    const int i = blockIdx.x * 256 + threadIdx.x;
    if (i < DMOD)            out[i] = a[i];
    else if (i < 2 * DMOD)   out[i] = b[i - DMOD];
    else if (i < 3 * DMOD)   out[i] = c[i - 2 * DMOD];
}

// ---------------------------------------------------------------------------
// Flash attention, b=0 only. Grid (S/64, H), 256 threads. ldq = QKV row stride.
// ---------------------------------------------------------------------------
__global__ __launch_bounds__(256, 2)
void flash_attn(const float* __restrict__ Q, const float* __restrict__ K,
                const float* __restrict__ V, int ldq, float* __restrict__ O)
{
    __shared__ float Qs[64 * 64];
    __shared__ float Ks[64 * 64];
    __shared__ float Vs[64 * 64];

    const int tid = threadIdx.x;
    const int tx  = tid & 15;
    const int ty  = tid >> 4;
    const int h   = blockIdx.y;
    const int q0  = blockIdx.x * 64;

    const int lr = tid >> 4;
    const int lc = (tid & 15) << 2;

    #pragma unroll
    for (int rr = 0; rr < 4; ++rr) {
        const int r = lr + rr * 16;
        float4 v4 = *(const float4*)(Q + (size_t)(q0 + r) * ldq + h * DH + lc);
        *(float4*)&Qs[r * 64 + lc] = v4;
    }

    const int qr0 = ty * 4;
    const int kc0 = tx * 4;

    float m[4], l[4], o[4][4];
    #pragma unroll
    for (int i = 0; i < 4; ++i) {
        m[i] = -1e30f; l[i] = 0.0f;
        #pragma unroll
        for (int j = 0; j < 4; ++j) o[i][j] = 0.0f;
    }

    for (int kt = 0; kt < SEQ; kt += 64) {
        #pragma unroll
        for (int rr = 0; rr < 4; ++rr) {
            const int r  = lr + rr * 16;
            const int sw = (r >> 3) << 2;
            float4 kv = *(const float4*)(K + (size_t)(kt + r) * ldq + h * DH + lc);
            *(float4*)&Ks[r * 64 + (lc ^ sw)] = kv;
            float4 vv = *(const float4*)(V + (size_t)(kt + r) * ldq + h * DH + lc);
            *(float4*)&Vs[r * 64 + lc] = vv;
        }
        __syncthreads();

        float s[4][4];
        #pragma unroll
        for (int i = 0; i < 4; ++i)
            #pragma unroll
            for (int j = 0; j < 4; ++j) s[i][j] = 0.0f;

        #pragma unroll 4
        for (int d = 0; d < 64; d += 4) {
            float a[4][4], b[4][4];
            #pragma unroll
            for (int i = 0; i < 4; ++i) {
                float4 tq = *(const float4*)&Qs[(qr0 + i) * 64 + d];
                a[i][0] = tq.x; a[i][1] = tq.y; a[i][2] = tq.z; a[i][3] = tq.w;
            }
            #pragma unroll
            for (int j = 0; j < 4; ++j) {
                const int kr = kc0 + j;
                const int sw = (kr >> 3) << 2;
                float4 tk = *(const float4*)&Ks[kr * 64 + (d ^ sw)];
                b[j][0] = tk.x; b[j][1] = tk.y; b[j][2] = tk.z; b[j][3] = tk.w;
            }
            #pragma unroll
            for (int i = 0; i < 4; ++i)
                #pragma unroll
                for (int j = 0; j < 4; ++j)
                    s[i][j] += a[i][0]*b[j][0] + a[i][1]*b[j][1]
                             + a[i][2]*b[j][2] + a[i][3]*b[j][3];
        }
        __syncthreads();

        #pragma unroll
        for (int i = 0; i < 4; ++i) {
            #pragma unroll
            for (int j = 0; j < 4; ++j) s[i][j] *= 0.125f;

            float rm = fmaxf(fmaxf(s[i][0], s[i][1]), fmaxf(s[i][2], s[i][3]));
            #pragma unroll
            for (int w = 8; w; w >>= 1)
                rm = fmaxf(rm, __shfl_xor_sync(0xffffffffu, rm, w));

            const float nm   = fmaxf(m[i], rm);
            const float corr = __expf(m[i] - nm);
            m[i] = nm;

            float rs = 0.0f;
            #pragma unroll
            for (int j = 0; j < 4; ++j) {
                s[i][j] = __expf(s[i][j] - nm);
                rs += s[i][j];
            }
            #pragma unroll
            for (int w = 8; w; w >>= 1)
                rs += __shfl_xor_sync(0xffffffffu, rs, w);

            l[i] = l[i] * corr + rs;
            #pragma unroll
            for (int j = 0; j < 4; ++j) o[i][j] *= corr;

            *(float4*)&Ks[(qr0 + i) * 64 + kc0] =
                make_float4(s[i][0], s[i][1], s[i][2], s[i][3]);
        }
        __syncthreads();

        #pragma unroll 4
        for (int kk = 0; kk < 64; kk += 4) {
            float p[4][4], vr[4][4];
            #pragma unroll
            for (int i = 0; i < 4; ++i) {
                float4 tp = *(const float4*)&Ks[(qr0 + i) * 64 + kk];
                p[i][0] = tp.x; p[i][1] = tp.y; p[i][2] = tp.z; p[i][3] = tp.w;
            }
            #pragma unroll
            for (int c = 0; c < 4; ++c) {
                float4 tv = *(const float4*)&Vs[(kk + c) * 64 + kc0];
                vr[c][0] = tv.x; vr[c][1] = tv.y; vr[c][2] = tv.z; vr[c][3] = tv.w;
            }
            #pragma unroll
            for (int i = 0; i < 4; ++i)
                #pragma unroll
                for (int j = 0; j < 4; ++j)
                    o[i][j] += p[i][0]*vr[0][j] + p[i][1]*vr[1][j]
                             + p[i][2]*vr[2][j] + p[i][3]*vr[3][j];
        }
        __syncthreads();
    }

    #pragma unroll
    for (int i = 0; i < 4; ++i) {
        const float inv = 1.0f / l[i];
        float4 ov = make_float4(o[i][0]*inv, o[i][1]*inv, o[i][2]*inv, o[i][3]*inv);
        *(float4*)(O + (size_t)(q0 + qr0 + i) * DMOD + h * DH + kc0) = ov;
    }
}

// ---------------------------------------------------------------------------
// out[row] = LayerNorm(a[row] + b[row % bwrap]) * g + beta
// ---------------------------------------------------------------------------
__global__ __launch_bounds__(256)
void ln_add(const float* __restrict__ a, const float* __restrict__ b, int bwrap,
            const float* __restrict__ g, const float* __restrict__ be,
            float* __restrict__ out)
{
    const int row  = blockIdx.x;
    const int brow = row % bwrap;
    const int t    = threadIdx.x;

    float4 av = ((const float4*)(a + (size_t)row  * DMOD))[t];
    float4 bv = ((const float4*)(b + (size_t)brow * DMOD))[t];
    const float x0 = av.x + bv.x, x1 = av.y + bv.y;
    const float x2 = av.z + bv.z, x3 = av.w + bv.w;

    float s  = x0 + x1 + x2 + x3;
    float ss = x0*x0 + x1*x1 + x2*x2 + x3*x3;

    #pragma unroll
    for (int w = 16; w; w >>= 1) {
        s  += __shfl_xor_sync(0xffffffffu, s,  w);
        ss += __shfl_xor_sync(0xffffffffu, ss, w);
    }

    __shared__ float rs[8], rss[8];
    if ((t & 31) == 0) { rs[t >> 5] = s; rss[t >> 5] = ss; }
    __syncthreads();

    float tot = 0.0f, tot2 = 0.0f;
    #pragma unroll
    for (int i = 0; i < 8; ++i) { tot += rs[i]; tot2 += rss[i]; }

    const float mu  = tot  * (1.0f / DMOD);
    const float var = tot2 * (1.0f / DMOD) - mu * mu;
    const float inv = rsqrtf(var + 1e-5f);

    float4 gv = ((const float4*)g )[t];
    float4 ev = ((const float4*)be)[t];
    float4 ov;
    ov.x = (x0 - mu) * inv * gv.x + ev.x;
    ov.y = (x1 - mu) * inv * gv.y + ev.y;
    ov.z = (x2 - mu) * inv * gv.z + ev.z;
    ov.w = (x3 - mu) * inv * gv.w + ev.w;
    ((float4*)(out + (size_t)row * DMOD))[t] = ov;
}

// ---------------------------------------------------------------------------
extern "C" void kernel_launch(void* const* d_in, const int* in_sizes, int n_in,
                              void* d_out, int out_size)
{
    (void)in_sizes; (void)n_in; (void)out_size;

    const float* src  = (const float*)d_in[0];
    const float* w_q  = (const float*)d_in[1];
    const float* b_q  = (const float*)d_in[2];
    const float* w_k  = (const float*)d_in[3];
    const float* b_k  = (const float*)d_in[4];
    const float* w_v  = (const float*)d_in[5];
    const float* b_v  = (const float*)d_in[6];
    const float* w_o  = (const float*)d_in[7];
    const float* b_o  = (const float*)d_in[8];
    const float* ln1g = (const float*)d_in[9];
    const float* ln1b = (const float*)d_in[10];
    const float* ln2g = (const float*)d_in[11];
    const float* ln2b = (const float*)d_in[12];
    const float* w1   = (const float*)d_in[13];
    const float* bb1  = (const float*)d_in[14];
    const float* w2   = (const float*)d_in[15];
    const float* bb2  = (const float*)d_in[16];
    float* out = (float*)d_out;

    bf16 *src_h, *src_l, *wqkv_h, *wqkv_l, *wo_h, *wo_l, *w1_h, *w1_l, *w2_h, *w2_l;
    bf16 *ctx_h, *ctx_l, *x_h, *x_l, *h1_h, *h1_l;
    float *bqkv, *qkv, *ctx, *att, *x, *h1, *f2;
    cudaGetSymbolAddress((void**)&src_h,  g_src_h);  cudaGetSymbolAddress((void**)&src_l,  g_src_l);
    cudaGetSymbolAddress((void**)&wqkv_h, g_wqkv_h); cudaGetSymbolAddress((void**)&wqkv_l, g_wqkv_l);
    cudaGetSymbolAddress((void**)&bqkv,   g_bqkv);
    cudaGetSymbolAddress((void**)&wo_h,   g_wo_h);   cudaGetSymbolAddress((void**)&wo_l,   g_wo_l);
    cudaGetSymbolAddress((void**)&w1_h,   g_w1_h);   cudaGetSymbolAddress((void**)&w1_l,   g_w1_l);
    cudaGetSymbolAddress((void**)&w2_h,   g_w2_h);   cudaGetSymbolAddress((void**)&w2_l,   g_w2_l);
    cudaGetSymbolAddress((void**)&qkv,    g_qkv);
    cudaGetSymbolAddress((void**)&ctx,    g_ctx);
    cudaGetSymbolAddress((void**)&ctx_h,  g_ctx_h);  cudaGetSymbolAddress((void**)&ctx_l,  g_ctx_l);
    cudaGetSymbolAddress((void**)&att,    g_att);
    cudaGetSymbolAddress((void**)&x,      g_x);
    cudaGetSymbolAddress((void**)&x_h,    g_x_h);    cudaGetSymbolAddress((void**)&x_l,    g_x_l);
    cudaGetSymbolAddress((void**)&h1,     g_h1);
    cudaGetSymbolAddress((void**)&h1_h,   g_h1_h);   cudaGetSymbolAddress((void**)&h1_l,   g_h1_l);
    cudaGetSymbolAddress((void**)&f2,     g_f2);

    cudaFuncSetAttribute(gemm_mma, cudaFuncAttributeMaxDynamicSharedMemorySize, GM_SMEM);

    const dim3 tb(32, 8);

    // --- operand prep (weights + src) ---
    trans_split<<<dim3(DMOD/32, DMOD/32), tb>>>(w_q, wqkv_h, wqkv_l, DMOD, DMOD, 0,      DMOD);
    trans_split<<<dim3(DMOD/32, DMOD/32), tb>>>(w_k, wqkv_h, wqkv_l, DMOD, DMOD, DMOD,   DMOD);
    trans_split<<<dim3(DMOD/32, DMOD/32), tb>>>(w_v, wqkv_h, wqkv_l, DMOD, DMOD, 2*DMOD, DMOD);
    trans_split<<<dim3(DMOD/32, DMOD/32), tb>>>(w_o, wo_h,   wo_l,   DMOD, DMOD, 0,      DMOD);
    trans_split<<<dim3(DFF/32,  DMOD/32), tb>>>(w1,  w1_h,   w1_l,   DMOD, DFF,  0,      DMOD);
    trans_split<<<dim3(DMOD/32, DFF/32),  tb>>>(w2,  w2_h,   w2_l,   DFF,  DMOD, 0,      DFF);
    pack_bias3<<<12, 256>>>(b_q, b_k, b_v, bqkv);
    split_f32<<<(M_ATT*DMOD/4 + 255)/256, 256>>>((const float4*)src, src_h, src_l, M_ATT*DMOD/4);

    // --- QKV: [2048,1024] @ [1024,3072] -> qkv [2048,3072] ---
    gemm_mma<<<dim3(3*DMOD/128, M_ATT/128), 256, GM_SMEM>>>(
        src_h, src_l, wqkv_h, wqkv_l, bqkv, qkv, M_ATT, 3*DMOD, DMOD, 0);

    // --- attention (batch 0) ---
    flash_attn<<<dim3(SEQ/64, NHEAD), 256>>>(qkv, qkv + DMOD, qkv + 2*DMOD, 3*DMOD, ctx);

    // --- out-proj ---
    split_f32<<<(M_ATT*DMOD/4 + 255)/256, 256>>>((const float4*)ctx, ctx_h, ctx_l, M_ATT*DMOD/4);
    gemm_mma<<<dim3(DMOD/128, M_ATT/128), 256, GM_SMEM>>>(
        ctx_h, ctx_l, wo_h, wo_l, b_o, att, M_ATT, DMOD, DMOD, 0);

    // --- x = LN1(src + attn_out[0] broadcast) ---
    ln_add<<<M_ALL, 256>>>(src, att, SEQ, ln1g, ln1b, x);

    // --- FFN ---
    split_f32<<<(M_ALL*DMOD/4 + 255)/256, 256>>>((const float4*)x, x_h, x_l, M_ALL*DMOD/4);
    gemm_mma<<<dim3(DFF/128, M_ALL/128), 256, GM_SMEM>>>(
        x_h, x_l, w1_h, w1_l, bb1, h1, M_ALL, DFF, DMOD, 1);
    split_f32<<<(M_ALL*DFF/4 + 255)/256, 256>>>((const float4*)h1, h1_h, h1_l, M_ALL*DFF/4);
    gemm_mma<<<dim3(DMOD/128, M_ALL/128), 256, GM_SMEM>>>(
        h1_h, h1_l, w2_h, w2_l, bb2, f2, M_ALL, DMOD, DFF, 0);

    // --- out = LN2(x + ffn) ---
    ln_add<<<M_ALL, 256>>>(x, f2, M_ALL, ln2g, ln2b, out);
}

// round 8
// speedup vs baseline: 2.6578x; 1.5449x over previous
#include <cuda_runtime.h>
#include <cuda_bf16.h>
#include <math.h>
#include <stdint.h>

// ---------------------------------------------------------------------------
// TransformerEncoderLayer: B=2, S=2048, D=1024, H=16, dh=64, F=2048, fp32.
// Only batch 0 of attention output is used (src2 = attn_out[0]).
// All GEMMs + attention matmuls on HMMA (mma.sync m16n8k16 bf16) with 2-term
// bf16 hi/lo split (hi*hi + lo*hi + hi*lo) for ~1e-5 accuracy.
// Softmax exp via FMA-pipe polynomial (no MUFU). LayerNorm fp32 SIMT.
// ---------------------------------------------------------------------------

#define SEQ   2048
#define DMOD  1024
#define DFF   2048
#define NHEAD 16
#define DH    64
#define M_ATT 2048
#define M_ALL 4096

typedef __nv_bfloat16 bf16;

// ------------------------- scratch (device globals) ------------------------
__device__ bf16  g_src_h[M_ATT * DMOD],  g_src_l[M_ATT * DMOD];
__device__ bf16  g_wqkv_h[3 * DMOD * DMOD], g_wqkv_l[3 * DMOD * DMOD]; // [3072,1024] K-major
__device__ float g_bqkv[3 * DMOD];
__device__ bf16  g_wo_h[DMOD * DMOD],   g_wo_l[DMOD * DMOD];
__device__ bf16  g_w1_h[DFF * DMOD],    g_w1_l[DFF * DMOD];
__device__ bf16  g_w2_h[DMOD * DFF],    g_w2_l[DMOD * DFF];
__device__ bf16  g_qkv_h[M_ATT * 3 * DMOD], g_qkv_l[M_ATT * 3 * DMOD]; // [2048,3072]
__device__ bf16  g_vt_h[DMOD * SEQ],    g_vt_l[DMOD * SEQ];            // V^T [1024,2048]
__device__ bf16  g_ctx_h[M_ATT * DMOD], g_ctx_l[M_ATT * DMOD];
__device__ float g_att[M_ATT * DMOD];
__device__ float g_x  [M_ALL * DMOD];
__device__ bf16  g_x_h [M_ALL * DMOD],  g_x_l [M_ALL * DMOD];
__device__ bf16  g_h1_h[M_ALL * DFF],   g_h1_l[M_ALL * DFF];
__device__ float g_f2 [M_ALL * DMOD];

// ------------------------------ helpers ------------------------------------
__device__ __forceinline__ uint32_t smem_to_u32(const void* p) {
    uint32_t a;
    asm("{ .reg .u64 t; cvta.to.shared.u64 t, %1; cvt.u32.u64 %0, t; }"
        : "=r"(a) : "l"(p));
    return a;
}
__device__ __forceinline__ void cp16(uint32_t d, const void* s) {
    asm volatile("cp.async.cg.shared.global [%0], [%1], 16;" :: "r"(d), "l"(s));
}
__device__ __forceinline__ void ldsm4(uint32_t r[4], uint32_t addr) {
    asm volatile("ldmatrix.sync.aligned.m8n8.x4.shared.b16 {%0,%1,%2,%3}, [%4];"
                 : "=r"(r[0]), "=r"(r[1]), "=r"(r[2]), "=r"(r[3]) : "r"(addr));
}
#define MMA16816(d, a, b0, b1) \
    asm volatile("mma.sync.aligned.m16n8k16.row.col.f32.bf16.bf16.f32 " \
        "{%0,%1,%2,%3}, {%4,%5,%6,%7}, {%8,%9}, {%0,%1,%2,%3};" \
        : "+f"((d)[0]), "+f"((d)[1]), "+f"((d)[2]), "+f"((d)[3]) \
        : "r"((a)[0]), "r"((a)[1]), "r"((a)[2]), "r"((a)[3]), \
          "r"(b0), "r"(b1))

// 64B-row tile swizzle (4 segs) — used by gemm_mma (verified)
#define SWZ(row, seg) (((row) << 6) + (((seg) ^ (((row) >> 1) & 3)) << 4))
// 128B-row tile swizzle (8 segs) — attention tiles, conflict-free ldmatrix
#define SWZ8(row, seg) (((row) << 7) + ((((seg) ^ ((row) & 7))) << 4))

__device__ __forceinline__ float gelu_exact(float x) {
    return 0.5f * x * (1.0f + erff(x * 0.70710678118654752f));
}
__device__ __forceinline__ uint32_t pack_bf16x2(float a, float b) {
    __nv_bfloat162 h = __floats2bfloat162_rn(a, b);
    return *reinterpret_cast<uint32_t*>(&h);
}
__device__ __forceinline__ float2 unpack_bf16x2(uint32_t u) {
    __nv_bfloat162 h = *reinterpret_cast<__nv_bfloat162*>(&u);
    return __bfloat1622float2(h);
}
// exp(x) for x <= 0, FMA/ALU pipes only, rel err ~2e-6
__device__ __forceinline__ float fexp(float x) {
    x = fmaxf(x, -87.0f);
    const float L2E = 1.4426950408889634f;
    float t = fmaf(x, L2E, 12582912.0f);
    float n = t - 12582912.0f;
    float r = fmaf(x, L2E, -n);
    float p = 0.0013333558f;
    p = fmaf(p, r, 0.0096181291f);
    p = fmaf(p, r, 0.0555041087f);
    p = fmaf(p, r, 0.2402265069f);
    p = fmaf(p, r, 0.6931471806f);
    p = fmaf(p, r, 1.0f);
    int ni = __float_as_int(t) - 0x4B400000;     // = round(x*log2e)
    return p * __int_as_float((ni + 127) << 23);
}

// ---------------------------------------------------------------------------
// HMMA GEMM: out = act((Asplit @ Bsplit^T + bias) [* scaleVal for col<scaleEnd])
//   A*: [M,K] bf16 K-major (hi,lo); B*: [N,K] bf16 K-major (hi,lo).
// Outputs: Cf (f32, nullable) and/or Chi/Clo (bf16 split, nullable).
// CTA 128x128, 8 warps, K-chunk 32, cp.async double-buffered.
// ---------------------------------------------------------------------------
#define GM_SMEM 65536

__global__ __launch_bounds__(256, 1)
void gemm_mma(const bf16* __restrict__ Ahi, const bf16* __restrict__ Alo,
              const bf16* __restrict__ Bhi, const bf16* __restrict__ Blo,
              const float* __restrict__ bias,
              float* __restrict__ Cf, bf16* __restrict__ Chi, bf16* __restrict__ Clo,
              int M, int N, int K, int act, int scaleEnd, float scaleVal)
{
    extern __shared__ char sm[];
    const uint32_t smb = smem_to_u32(sm);
    const int tid  = threadIdx.x;
    const int lane = tid & 31;
    const int wid  = tid >> 5;
    const int wm   = wid >> 2;
    const int wn   = wid & 3;
    const int m0 = blockIdx.y * 128;
    const int n0 = blockIdx.x * 128;

    const char* gAh = (const char*)(Ahi + (size_t)m0 * K);
    const char* gAl = (const char*)(Alo + (size_t)m0 * K);
    const char* gBh = (const char*)(Bhi + (size_t)n0 * K);
    const char* gBl = (const char*)(Blo + (size_t)n0 * K);

    const int lrow = tid >> 2;
    const int lseg = tid & 3;

    float acc[4][4][4];
    #pragma unroll
    for (int i = 0; i < 4; ++i)
        #pragma unroll
        for (int j = 0; j < 4; ++j)
            #pragma unroll
            for (int q = 0; q < 4; ++q) acc[i][j][q] = 0.0f;

    const int nch = K >> 5;

    auto issue = [&](int ch, int buf) {
        const int k0 = ch << 5;
        #pragma unroll
        for (int i = 0; i < 2; ++i) {
            const int row = lrow + (i << 6);
            const uint32_t so = SWZ(row, lseg) + (uint32_t)buf * 32768 + smb;
            const size_t go = (size_t)row * K * 2 + (size_t)(k0 + lseg * 8) * 2;
            cp16(so +     0, gAh + go);
            cp16(so +  8192, gAl + go);
            cp16(so + 16384, gBh + go);
            cp16(so + 24576, gBl + go);
        }
        asm volatile("cp.async.commit_group;" ::: "memory");
    };

    issue(0, 0);

    const int arow = wm * 64 + (lane & 15);
    const int aseg0 = (lane >> 4);
    const int brow = wn * 32 + (lane & 7) + ((lane >> 4) & 1) * 8;
    const int bseg0 = ((lane >> 3) & 1);

    for (int ch = 0; ch < nch; ++ch) {
        const int buf = ch & 1;
        if (ch + 1 < nch) {
            issue(ch + 1, buf ^ 1);
            asm volatile("cp.async.wait_group 1;" ::: "memory");
        } else {
            asm volatile("cp.async.wait_group 0;" ::: "memory");
        }
        __syncthreads();

        const uint32_t Ah = smb + (uint32_t)buf * 32768;
        const uint32_t Al = Ah + 8192;
        const uint32_t Bh = Ah + 16384;
        const uint32_t Bl = Ah + 24576;

        #pragma unroll
        for (int ks = 0; ks < 2; ++ks) {
            const int asg = ks * 2 + aseg0;
            const int bsg = ks * 2 + bseg0;
            uint32_t af[4][4], al[4][4], bfr[4][2];

            #pragma unroll
            for (int ti = 0; ti < 4; ++ti)
                ldsm4(af[ti], Ah + SWZ(arow + ti * 16, asg));
            #pragma unroll
            for (int p = 0; p < 2; ++p) {
                uint32_t r[4];
                ldsm4(r, Bh + SWZ(brow + p * 16, bsg));
                bfr[2*p][0] = r[0]; bfr[2*p][1] = r[1];
                bfr[2*p+1][0] = r[2]; bfr[2*p+1][1] = r[3];
            }
            #pragma unroll
            for (int ti = 0; ti < 4; ++ti)
                #pragma unroll
                for (int tj = 0; tj < 4; ++tj)
                    MMA16816(acc[ti][tj], af[ti], bfr[tj][0], bfr[tj][1]);

            #pragma unroll
            for (int ti = 0; ti < 4; ++ti)
                ldsm4(al[ti], Al + SWZ(arow + ti * 16, asg));
            #pragma unroll
            for (int ti = 0; ti < 4; ++ti)
                #pragma unroll
                for (int tj = 0; tj < 4; ++tj)
                    MMA16816(acc[ti][tj], al[ti], bfr[tj][0], bfr[tj][1]);

            #pragma unroll
            for (int p = 0; p < 2; ++p) {
                uint32_t r[4];
                ldsm4(r, Bl + SWZ(brow + p * 16, bsg));
                bfr[2*p][0] = r[0]; bfr[2*p][1] = r[1];
                bfr[2*p+1][0] = r[2]; bfr[2*p+1][1] = r[3];
            }
            #pragma unroll
            for (int ti = 0; ti < 4; ++ti)
                #pragma unroll
                for (int tj = 0; tj < 4; ++tj)
                    MMA16816(acc[ti][tj], af[ti], bfr[tj][0], bfr[tj][1]);
        }
        __syncthreads();
    }

    // --- epilogue ---
    const int g = lane >> 2, t = lane & 3;
    #pragma unroll
    for (int tj = 0; tj < 4; ++tj) {
        const int c = n0 + wn * 32 + tj * 8 + 2 * t;
        const float2 b2 = *(const float2*)&bias[c];
        const bool dsc = (c < scaleEnd);
        #pragma unroll
        for (int ti = 0; ti < 4; ++ti) {
            const int r0 = m0 + wm * 64 + ti * 16 + g;
            float2 v0 = make_float2(acc[ti][tj][0] + b2.x, acc[ti][tj][1] + b2.y);
            float2 v1 = make_float2(acc[ti][tj][2] + b2.x, acc[ti][tj][3] + b2.y);
            if (dsc) { v0.x *= scaleVal; v0.y *= scaleVal; v1.x *= scaleVal; v1.y *= scaleVal; }
            if (act) {
                v0.x = gelu_exact(v0.x); v0.y = gelu_exact(v0.y);
                v1.x = gelu_exact(v1.x); v1.y = gelu_exact(v1.y);
            }
            if (Cf) {
                *(float2*)(Cf + (size_t)r0 * N + c) = v0;
                *(float2*)(Cf + (size_t)(r0 + 8) * N + c) = v1;
            }
            if (Chi) {
                uint32_t h0 = pack_bf16x2(v0.x, v0.y);
                float2 f0 = unpack_bf16x2(h0);
                uint32_t l0 = pack_bf16x2(v0.x - f0.x, v0.y - f0.y);
                uint32_t h1 = pack_bf16x2(v1.x, v1.y);
                float2 f1 = unpack_bf16x2(h1);
                uint32_t l1 = pack_bf16x2(v1.x - f1.x, v1.y - f1.y);
                *(uint32_t*)(Chi + (size_t)r0 * N + c) = h0;
                *(uint32_t*)(Clo + (size_t)r0 * N + c) = l0;
                *(uint32_t*)(Chi + (size_t)(r0 + 8) * N + c) = h1;
                *(uint32_t*)(Clo + (size_t)(r0 + 8) * N + c) = l1;
            }
        }
    }
}

// ---------------------------------------------------------------------------
// HMMA flash attention, batch 0. Grid (S/64, H), 128 threads (4 warps).
// Q,K from qkv hi/lo bf16 [S,3072] (Q pre-scaled by 0.125 in GEMM epilogue);
// V from pre-transposed vt hi/lo [1024,2048]. Output ctx hi/lo bf16 [S,1024].
// smem: Qh(8K) Ql(8K) + 2 x [Kh Kl Vh Vl](32K) = 80KB.
// ---------------------------------------------------------------------------
#define FA_SMEM (16384 + 2 * 32768)

__global__ __launch_bounds__(128, 1)
void flash_mma(const bf16* __restrict__ qh, const bf16* __restrict__ ql,
               const bf16* __restrict__ vth, const bf16* __restrict__ vtl,
               bf16* __restrict__ ch, bf16* __restrict__ cl)
{
    extern __shared__ char sm[];
    const uint32_t smb = smem_to_u32(sm);
    const int tid  = threadIdx.x;
    const int lane = tid & 31;
    const int w    = tid >> 5;
    const int h    = blockIdx.y;
    const int q0   = blockIdx.x * 64;

    // --- async loads (sid = tid*4+i: row = sid>>3, seg = sid&7) ---
    {   // Q tile (once)
        #pragma unroll
        for (int i = 0; i < 4; ++i) {
            const int sid = tid * 4 + i;
            const int row = sid >> 3, sg = sid & 7;
            const size_t go = (size_t)(q0 + row) * (3 * DMOD) + h * DH + sg * 8;
            cp16(smb + SWZ8(row, sg), qh + go);
            cp16(smb + 8192 + SWZ8(row, sg), ql + go);
        }
    }
    auto ldKV = [&](int kt, int buf) {
        const uint32_t base = smb + 16384 + (uint32_t)buf * 32768;
        #pragma unroll
        for (int i = 0; i < 4; ++i) {
            const int sid = tid * 4 + i;
            const int row = sid >> 3, sg = sid & 7;
            const size_t gk = (size_t)(kt + row) * (3 * DMOD) + DMOD + h * DH + sg * 8;
            cp16(base + SWZ8(row, sg), qh + gk);
            cp16(base + 8192 + SWZ8(row, sg), ql + gk);
            const size_t gv = (size_t)(h * DH + row) * SEQ + kt + sg * 8;
            cp16(base + 16384 + SWZ8(row, sg), vth + gv);
            cp16(base + 24576 + SWZ8(row, sg), vtl + gv);
        }
        asm volatile("cp.async.commit_group;" ::: "memory");
    };
    ldKV(0, 0);   // group 0 also covers Q loads

    const int arow = w * 16 + (lane & 15);
    const int aseg0 = lane >> 4;
    const int brow = (lane & 7) + ((lane >> 4) & 1) * 8;
    const int bseg0 = (lane >> 3) & 1;

    float m0r = -1e30f, m1r = -1e30f, l0r = 0.0f, l1r = 0.0f;
    float o[8][4];
    #pragma unroll
    for (int j = 0; j < 8; ++j)
        #pragma unroll
        for (int q = 0; q < 4; ++q) o[j][q] = 0.0f;

    const int NT = SEQ / 64;
    for (int kt = 0; kt < NT; ++kt) {
        const int buf = kt & 1;
        if (kt + 1 < NT) {
            ldKV((kt + 1) * 64, buf ^ 1);
            asm volatile("cp.async.wait_group 1;" ::: "memory");
        } else {
            asm volatile("cp.async.wait_group 0;" ::: "memory");
        }
        __syncthreads();

        const uint32_t Kh = smb + 16384 + (uint32_t)buf * 32768;
        const uint32_t Kl = Kh + 8192;
        const uint32_t Vh = Kh + 16384;
        const uint32_t Vl = Kh + 24576;

        // ---- scores S = (Qs) K^T  (pre-scaled Q) ----
        float s[8][4];
        #pragma unroll
        for (int j = 0; j < 8; ++j)
            #pragma unroll
            for (int q = 0; q < 4; ++q) s[j][q] = 0.0f;

        #pragma unroll
        for (int ks = 0; ks < 4; ++ks) {
            uint32_t af[4], al[4];
            ldsm4(af, smb + SWZ8(arow, 2 * ks + aseg0));
            ldsm4(al, smb + 8192 + SWZ8(arow, 2 * ks + aseg0));
            #pragma unroll
            for (int jp = 0; jp < 4; ++jp) {
                uint32_t rh[4], rl[4];
                ldsm4(rh, Kh + SWZ8(jp * 16 + brow, 2 * ks + bseg0));
                ldsm4(rl, Kl + SWZ8(jp * 16 + brow, 2 * ks + bseg0));
                MMA16816(s[2*jp],   af, rh[0], rh[1]);
                MMA16816(s[2*jp+1], af, rh[2], rh[3]);
                MMA16816(s[2*jp],   al, rh[0], rh[1]);
                MMA16816(s[2*jp+1], al, rh[2], rh[3]);
                MMA16816(s[2*jp],   af, rl[0], rl[1]);
                MMA16816(s[2*jp+1], af, rl[2], rl[3]);
            }
        }

        // ---- online softmax (rows g, g+8) ----
        float rm0 = -1e30f, rm1 = -1e30f;
        #pragma unroll
        for (int j = 0; j < 8; ++j) {
            rm0 = fmaxf(rm0, fmaxf(s[j][0], s[j][1]));
            rm1 = fmaxf(rm1, fmaxf(s[j][2], s[j][3]));
        }
        rm0 = fmaxf(rm0, __shfl_xor_sync(0xffffffffu, rm0, 1));
        rm0 = fmaxf(rm0, __shfl_xor_sync(0xffffffffu, rm0, 2));
        rm1 = fmaxf(rm1, __shfl_xor_sync(0xffffffffu, rm1, 1));
        rm1 = fmaxf(rm1, __shfl_xor_sync(0xffffffffu, rm1, 2));

        const float nm0 = fmaxf(m0r, rm0);
        const float nm1 = fmaxf(m1r, rm1);
        const float c0 = fexp(m0r - nm0);
        const float c1 = fexp(m1r - nm1);
        m0r = nm0; m1r = nm1;

        float sum0 = 0.0f, sum1 = 0.0f;
        #pragma unroll
        for (int j = 0; j < 8; ++j) {
            s[j][0] = fexp(s[j][0] - nm0);
            s[j][1] = fexp(s[j][1] - nm0);
            s[j][2] = fexp(s[j][2] - nm1);
            s[j][3] = fexp(s[j][3] - nm1);
            sum0 += s[j][0] + s[j][1];
            sum1 += s[j][2] + s[j][3];
        }
        sum0 += __shfl_xor_sync(0xffffffffu, sum0, 1);
        sum0 += __shfl_xor_sync(0xffffffffu, sum0, 2);
        sum1 += __shfl_xor_sync(0xffffffffu, sum1, 1);
        sum1 += __shfl_xor_sync(0xffffffffu, sum1, 2);
        l0r = l0r * c0 + sum0;
        l1r = l1r * c1 + sum1;

        #pragma unroll
        for (int j = 0; j < 8; ++j) {
            o[j][0] *= c0; o[j][1] *= c0;
            o[j][2] *= c1; o[j][3] *= c1;
        }

        // ---- O += P V  (P hi/lo from registers) ----
        #pragma unroll
        for (int ks = 0; ks < 4; ++ks) {
            uint32_t ph[4], pl[4];
            {
                ph[0] = pack_bf16x2(s[2*ks][0], s[2*ks][1]);
                float2 f = unpack_bf16x2(ph[0]);
                pl[0] = pack_bf16x2(s[2*ks][0] - f.x, s[2*ks][1] - f.y);
                ph[1] = pack_bf16x2(s[2*ks][2], s[2*ks][3]);
                f = unpack_bf16x2(ph[1]);
                pl[1] = pack_bf16x2(s[2*ks][2] - f.x, s[2*ks][3] - f.y);
                ph[2] = pack_bf16x2(s[2*ks+1][0], s[2*ks+1][1]);
                f = unpack_bf16x2(ph[2]);
                pl[2] = pack_bf16x2(s[2*ks+1][0] - f.x, s[2*ks+1][1] - f.y);
                ph[3] = pack_bf16x2(s[2*ks+1][2], s[2*ks+1][3]);
                f = unpack_bf16x2(ph[3]);
                pl[3] = pack_bf16x2(s[2*ks+1][2] - f.x, s[2*ks+1][3] - f.y);
            }
            #pragma unroll
            for (int jp = 0; jp < 4; ++jp) {
                uint32_t rh[4], rl[4];
                ldsm4(rh, Vh + SWZ8(jp * 16 + brow, 2 * ks + bseg0));
                ldsm4(rl, Vl + SWZ8(jp * 16 + brow, 2 * ks + bseg0));
                MMA16816(o[2*jp],   ph, rh[0], rh[1]);
                MMA16816(o[2*jp+1], ph, rh[2], rh[3]);
                MMA16816(o[2*jp],   pl, rh[0], rh[1]);
                MMA16816(o[2*jp+1], pl, rh[2], rh[3]);
                MMA16816(o[2*jp],   ph, rl[0], rl[1]);
                MMA16816(o[2*jp+1], ph, rl[2], rl[3]);
            }
        }
        __syncthreads();
    }

    // ---- epilogue: normalize, split, store ctx hi/lo ----
    const float inv0 = 1.0f / l0r;
    const float inv1 = 1.0f / l1r;
    const int g = lane >> 2, t4 = lane & 3;
    const int row0 = q0 + w * 16 + g;
    #pragma unroll
    for (int j = 0; j < 8; ++j) {
        const int col = h * DH + j * 8 + 2 * t4;
        float a0 = o[j][0] * inv0, a1 = o[j][1] * inv0;
        float b0 = o[j][2] * inv1, b1 = o[j][3] * inv1;
        uint32_t h0 = pack_bf16x2(a0, a1);
        float2 f0 = unpack_bf16x2(h0);
        uint32_t lo0 = pack_bf16x2(a0 - f0.x, a1 - f0.y);
        uint32_t h1 = pack_bf16x2(b0, b1);
        float2 f1 = unpack_bf16x2(h1);
        uint32_t lo1 = pack_bf16x2(b0 - f1.x, b1 - f1.y);
        *(uint32_t*)(ch + (size_t)row0 * DMOD + col) = h0;
        *(uint32_t*)(cl + (size_t)row0 * DMOD + col) = lo0;
        *(uint32_t*)(ch + (size_t)(row0 + 8) * DMOD + col) = h1;
        *(uint32_t*)(cl + (size_t)(row0 + 8) * DMOD + col) = lo1;
    }
}

// ---------------------------------------------------------------------------
// fp32 -> (hi, lo) bf16 split, elementwise (src only).
// ---------------------------------------------------------------------------
__global__ __launch_bounds__(256)
void split_f32(const float4* __restrict__ in, bf16* __restrict__ hi,
               bf16* __restrict__ lo, int n4)
{
    const int i = blockIdx.x * 256 + threadIdx.x;
    if (i >= n4) return;
    const float4 x = in[i];
    __nv_bfloat162 h01 = __floats2bfloat162_rn(x.x, x.y);
    __nv_bfloat162 h23 = __floats2bfloat162_rn(x.z, x.w);
    float2 f01 = __bfloat1622float2(h01);
    float2 f23 = __bfloat1622float2(h23);
    __nv_bfloat162 l01 = __floats2bfloat162_rn(x.x - f01.x, x.y - f01.y);
    __nv_bfloat162 l23 = __floats2bfloat162_rn(x.z - f23.x, x.w - f23.y);
    ((__nv_bfloat162*)hi)[2 * i]     = h01;
    ((__nv_bfloat162*)hi)[2 * i + 1] = h23;
    ((__nv_bfloat162*)lo)[2 * i]     = l01;
    ((__nv_bfloat162*)lo)[2 * i + 1] = l23;
}

// ---------------------------------------------------------------------------
// W[K,N] fp32 -> transposed hi/lo bf16 [rowOff+N, outLd].
// ---------------------------------------------------------------------------
__global__ __launch_bounds__(256)
void trans_split(const float* __restrict__ W, bf16* __restrict__ hi,
                 bf16* __restrict__ lo, int K, int N, int rowOff, int outLd)
{
    __shared__ float t[32][33];
    const int k0 = blockIdx.y * 32, n0 = blockIdx.x * 32;
    const int tx = threadIdx.x, ty = threadIdx.y;
    #pragma unroll
    for (int i = 0; i < 32; i += 8)
        t[ty + i][tx] = W[(size_t)(k0 + ty + i) * N + n0 + tx];
    __syncthreads();
    #pragma unroll
    for (int i = 0; i < 32; i += 8) {
        const float x = t[tx][ty + i];
        const bf16 h = __float2bfloat16(x);
        const bf16 l = __float2bfloat16(x - __bfloat162float(h));
        const size_t o = (size_t)(rowOff + n0 + ty + i) * outLd + k0 + tx;
        hi[o] = h;
        lo[o] = l;
    }
}

// ---------------------------------------------------------------------------
// V part of qkv (bf16, cols 2048..3071) -> V^T hi/lo [1024, 2048].
// ---------------------------------------------------------------------------
__global__ __launch_bounds__(256)
void trans_v(const bf16* __restrict__ vh, const bf16* __restrict__ vl,
             bf16* __restrict__ vth, bf16* __restrict__ vtl)
{
    __shared__ bf16 th[32][33], tl[32][33];
    const int d0 = blockIdx.x * 32, s0 = blockIdx.y * 32;
    const int tx = threadIdx.x, ty = threadIdx.y;
    #pragma unroll
    for (int i = 0; i < 32; i += 8) {
        const size_t gi = (size_t)(s0 + ty + i) * (3 * DMOD) + 2 * DMOD + d0 + tx;
        th[ty + i][tx] = vh[gi];
        tl[ty + i][tx] = vl[gi];
    }
    __syncthreads();
    #pragma unroll
    for (int i = 0; i < 32; i += 8) {
        const size_t o = (size_t)(d0 + ty + i) * SEQ + s0 + tx;
        vth[o] = th[tx][ty + i];
        vtl[o] = tl[tx][ty + i];
    }
}

__global__ void pack_bias3(const float* __restrict__ a, const float* __restrict__ b,
                           const float* __restrict__ c, float* __restrict__ out)
{
    const int i = blockIdx.x * 256 + threadIdx.x;
    if (i < DMOD)            out[i] = a[i];
    else if (i < 2 * DMOD)   out[i] = b[i - DMOD];
    else if (i < 3 * DMOD)   out[i] = c[i - 2 * DMOD];
}

// ---------------------------------------------------------------------------
// out = LayerNorm(a[row] + b[row % bwrap]) * g + beta; optional hi/lo split out.
// ---------------------------------------------------------------------------
__global__ __launch_bounds__(256)
void ln_add(const float* __restrict__ a, const float* __restrict__ b, int bwrap,
            const float* __restrict__ g, const float* __restrict__ be,
            float* __restrict__ out, bf16* __restrict__ oh, bf16* __restrict__ ol)
{
    const int row  = blockIdx.x;
    const int brow = row % bwrap;
    const int t    = threadIdx.x;

    float4 av = ((const float4*)(a + (size_t)row  * DMOD))[t];
    float4 bv = ((const float4*)(b + (size_t)brow * DMOD))[t];
    const float x0 = av.x + bv.x, x1 = av.y + bv.y;
    const float x2 = av.z + bv.z, x3 = av.w + bv.w;

    float s  = x0 + x1 + x2 + x3;
    float ss = x0*x0 + x1*x1 + x2*x2 + x3*x3;

    #pragma unroll
    for (int w = 16; w; w >>= 1) {
        s  += __shfl_xor_sync(0xffffffffu, s,  w);
        ss += __shfl_xor_sync(0xffffffffu, ss, w);
    }

    __shared__ float rs[8], rss[8];
    if ((t & 31) == 0) { rs[t >> 5] = s; rss[t >> 5] = ss; }
    __syncthreads();

    float tot = 0.0f, tot2 = 0.0f;
    #pragma unroll
    for (int i = 0; i < 8; ++i) { tot += rs[i]; tot2 += rss[i]; }

    const float mu  = tot  * (1.0f / DMOD);
    const float var = tot2 * (1.0f / DMOD) - mu * mu;
    const float inv = rsqrtf(var + 1e-5f);

    float4 gv = ((const float4*)g )[t];
    float4 ev = ((const float4*)be)[t];
    float4 ov;
    ov.x = (x0 - mu) * inv * gv.x + ev.x;
    ov.y = (x1 - mu) * inv * gv.y + ev.y;
    ov.z = (x2 - mu) * inv * gv.z + ev.z;
    ov.w = (x3 - mu) * inv * gv.w + ev.w;
    ((float4*)(out + (size_t)row * DMOD))[t] = ov;

    if (oh) {
        uint32_t h0 = pack_bf16x2(ov.x, ov.y);
        float2 f0 = unpack_bf16x2(h0);
        uint32_t l0 = pack_bf16x2(ov.x - f0.x, ov.y - f0.y);
        uint32_t h1 = pack_bf16x2(ov.z, ov.w);
        float2 f1 = unpack_bf16x2(h1);
        uint32_t l1 = pack_bf16x2(ov.z - f1.x, ov.w - f1.y);
        ((uint32_t*)(oh + (size_t)row * DMOD))[2 * t]     = h0;
        ((uint32_t*)(oh + (size_t)row * DMOD))[2 * t + 1] = h1;
        ((uint32_t*)(ol + (size_t)row * DMOD))[2 * t]     = l0;
        ((uint32_t*)(ol + (size_t)row * DMOD))[2 * t + 1] = l1;
    }
}

// ---------------------------------------------------------------------------
extern "C" void kernel_launch(void* const* d_in, const int* in_sizes, int n_in,
                              void* d_out, int out_size)
{
    (void)in_sizes; (void)n_in; (void)out_size;

    const float* src  = (const float*)d_in[0];
    const float* w_q  = (const float*)d_in[1];
    const float* b_q  = (const float*)d_in[2];
    const float* w_k  = (const float*)d_in[3];
    const float* b_k  = (const float*)d_in[4];
    const float* w_v  = (const float*)d_in[5];
    const float* b_v  = (const float*)d_in[6];
    const float* w_o  = (const float*)d_in[7];
    const float* b_o  = (const float*)d_in[8];
    const float* ln1g = (const float*)d_in[9];
    const float* ln1b = (const float*)d_in[10];
    const float* ln2g = (const float*)d_in[11];
    const float* ln2b = (const float*)d_in[12];
    const float* w1   = (const float*)d_in[13];
    const float* bb1  = (const float*)d_in[14];
    const float* w2   = (const float*)d_in[15];
    const float* bb2  = (const float*)d_in[16];
    float* out = (float*)d_out;

    bf16 *src_h, *src_l, *wqkv_h, *wqkv_l, *wo_h, *wo_l, *w1_h, *w1_l, *w2_h, *w2_l;
    bf16 *qkv_h, *qkv_l, *vt_h, *vt_l, *ctx_h, *ctx_l, *x_h, *x_l, *h1_h, *h1_l;
    float *bqkv, *att, *x, *f2;
    cudaGetSymbolAddress((void**)&src_h,  g_src_h);  cudaGetSymbolAddress((void**)&src_l,  g_src_l);
    cudaGetSymbolAddress((void**)&wqkv_h, g_wqkv_h); cudaGetSymbolAddress((void**)&wqkv_l, g_wqkv_l);
    cudaGetSymbolAddress((void**)&bqkv,   g_bqkv);
    cudaGetSymbolAddress((void**)&wo_h,   g_wo_h);   cudaGetSymbolAddress((void**)&wo_l,   g_wo_l);
    cudaGetSymbolAddress((void**)&w1_h,   g_w1_h);   cudaGetSymbolAddress((void**)&w1_l,   g_w1_l);
    cudaGetSymbolAddress((void**)&w2_h,   g_w2_h);   cudaGetSymbolAddress((void**)&w2_l,   g_w2_l);
    cudaGetSymbolAddress((void**)&qkv_h,  g_qkv_h);  cudaGetSymbolAddress((void**)&qkv_l,  g_qkv_l);
    cudaGetSymbolAddress((void**)&vt_h,   g_vt_h);   cudaGetSymbolAddress((void**)&vt_l,   g_vt_l);
    cudaGetSymbolAddress((void**)&ctx_h,  g_ctx_h);  cudaGetSymbolAddress((void**)&ctx_l,  g_ctx_l);
    cudaGetSymbolAddress((void**)&att,    g_att);
    cudaGetSymbolAddress((void**)&x,      g_x);
    cudaGetSymbolAddress((void**)&x_h,    g_x_h);    cudaGetSymbolAddress((void**)&x_l,    g_x_l);
    cudaGetSymbolAddress((void**)&h1_h,   g_h1_h);   cudaGetSymbolAddress((void**)&h1_l,   g_h1_l);
    cudaGetSymbolAddress((void**)&f2,     g_f2);

    cudaFuncSetAttribute(gemm_mma,  cudaFuncAttributeMaxDynamicSharedMemorySize, GM_SMEM);
    cudaFuncSetAttribute(flash_mma, cudaFuncAttributeMaxDynamicSharedMemorySize, FA_SMEM);

    const dim3 tb(32, 8);

    // --- operand prep ---
    trans_split<<<dim3(DMOD/32, DMOD/32), tb>>>(w_q, wqkv_h, wqkv_l, DMOD, DMOD, 0,      DMOD);
    trans_split<<<dim3(DMOD/32, DMOD/32), tb>>>(w_k, wqkv_h, wqkv_l, DMOD, DMOD, DMOD,   DMOD);
    trans_split<<<dim3(DMOD/32, DMOD/32), tb>>>(w_v, wqkv_h, wqkv_l, DMOD, DMOD, 2*DMOD, DMOD);
    trans_split<<<dim3(DMOD/32, DMOD/32), tb>>>(w_o, wo_h,   wo_l,   DMOD, DMOD, 0,      DMOD);
    trans_split<<<dim3(DFF/32,  DMOD/32), tb>>>(w1,  w1_h,   w1_l,   DMOD, DFF,  0,      DMOD);
    trans_split<<<dim3(DMOD/32, DFF/32),  tb>>>(w2,  w2_h,   w2_l,   DFF,  DMOD, 0,      DFF);
    pack_bias3<<<12, 256>>>(b_q, b_k, b_v, bqkv);
    split_f32<<<(M_ATT*DMOD/4 + 255)/256, 256>>>((const float4*)src, src_h, src_l, M_ATT*DMOD/4);

    // --- QKV projection -> bf16 hi/lo, Q cols pre-scaled by 1/8 ---
    gemm_mma<<<dim3(3*DMOD/128, M_ATT/128), 256, GM_SMEM>>>(
        src_h, src_l, wqkv_h, wqkv_l, bqkv,
        (float*)nullptr, qkv_h, qkv_l,
        M_ATT, 3*DMOD, DMOD, 0, DMOD, 0.125f);

    // --- V transpose for attention B-operand ---
    trans_v<<<dim3(DMOD/32, SEQ/32), tb>>>(qkv_h, qkv_l, vt_h, vt_l);

    // --- attention (batch 0) -> ctx hi/lo ---
    flash_mma<<<dim3(SEQ/64, NHEAD), 128, FA_SMEM>>>(qkv_h, qkv_l, vt_h, vt_l, ctx_h, ctx_l);

    // --- out-proj -> att f32 ---
    gemm_mma<<<dim3(DMOD/128, M_ATT/128), 256, GM_SMEM>>>(
        ctx_h, ctx_l, wo_h, wo_l, b_o,
        att, (bf16*)nullptr, (bf16*)nullptr,
        M_ATT, DMOD, DMOD, 0, 0, 1.0f);

    // --- x = LN1(src + att broadcast), emit f32 + hi/lo ---
    ln_add<<<M_ALL, 256>>>(src, att, SEQ, ln1g, ln1b, x, x_h, x_l);

    // --- FFN1 (gelu) -> h1 hi/lo only ---
    gemm_mma<<<dim3(DFF/128, M_ALL/128), 256, GM_SMEM>>>(
        x_h, x_l, w1_h, w1_l, bb1,
        (float*)nullptr, h1_h, h1_l,
        M_ALL, DFF, DMOD, 1, 0, 1.0f);

    // --- FFN2 -> f2 f32 ---
    gemm_mma<<<dim3(DMOD/128, M_ALL/128), 256, GM_SMEM>>>(
        h1_h, h1_l, w2_h, w2_l, bb2,
        f2, (bf16*)nullptr, (bf16*)nullptr,
        M_ALL, DMOD, DFF, 0, 0, 1.0f);

    // --- out = LN2(x + ffn) ---
    ln_add<<<M_ALL, 256>>>(x, f2, M_ALL, ln2g, ln2b, out, (bf16*)nullptr, (bf16*)nullptr);
}